// round 15
// baseline (speedup 1.0000x reference)
#include <cuda_runtime.h>
#include <cstdint>

#define NV 778
#define NF 1538
#define NB 4
#define OW 128
#define OH 128
#define BGD 1e10f
#define CHUNK 13
#define NSLICE ((NF + CHUNK - 1) / CHUNK)         // 119
#define NPIX (NB * OH * OW)                       // 65536

// Precomputed face records (SoA): bbox + 4 float4 (e0,e1,e2,wv) per (b,f).
//   e: (s*dx, -(s*dy), refx, -refy)
//      e' = (s*dx)*(py + (-refy)) + [(-s*dy)*(px - refx)]
//   wv: (z0/|area|, z1/|area|, z2/|area|, 0)
__device__ float4 g_bb[NB * NF];
__device__ float4 g_ed[NB * NF * 4];

// Packed f32x2 helpers: component-wise IEEE-RN, bit-identical to scalar RN ops.
__device__ __forceinline__ unsigned long long pk2(float lo, float hi) {
    unsigned long long r;
    asm("mov.b64 %0, {%1, %2};" : "=l"(r) : "r"(__float_as_uint(lo)), "r"(__float_as_uint(hi)));
    return r;
}
__device__ __forceinline__ unsigned long long mul2(unsigned long long a, unsigned long long b) {
    unsigned long long r;
    asm("mul.rn.f32x2 %0, %1, %2;" : "=l"(r) : "l"(a), "l"(b));
    return r;
}
__device__ __forceinline__ unsigned long long add2(unsigned long long a, unsigned long long b) {
    unsigned long long r;
    asm("add.rn.f32x2 %0, %1, %2;" : "=l"(r) : "l"(a), "l"(b));
    return r;
}
__device__ __forceinline__ void unpk2(unsigned long long v, float& lo, float& hi) {
    unsigned int a, b;
    asm("mov.b64 {%0, %1}, %2;" : "=r"(a), "=r"(b) : "l"(v));
    lo = __uint_as_float(a); hi = __uint_as_float(b);
}

// Fused precompute: fill out with 100.0f AND build all face records.
__global__ void __launch_bounds__(256) setup_kernel(
    const float* __restrict__ verts, const int* __restrict__ faces,
    float* __restrict__ out)
{
    int idx = blockIdx.x * blockDim.x + threadIdx.x;

    if (idx < NPIX / 4) {
        float4 v = make_float4(100.0f, 100.0f, 100.0f, 100.0f);
        reinterpret_cast<float4*>(out)[idx] = v;
    }

    if (idx >= NB * NF) return;
    int b = idx / NF;
    int f = idx - b * NF;

    // faces land on device as int32 (JAX x64 disabled). Clamp defensively.
    int i0 = min(max(faces[f * 3 + 0], 0), NV - 1);
    int i1 = min(max(faces[f * 3 + 1], 0), NV - 1);
    int i2 = min(max(faces[f * 3 + 2], 0), NV - 1);
    const float* vb = verts + (size_t)b * NV * 3;
    float x0 = vb[i0 * 3 + 0], y0 = vb[i0 * 3 + 1], z0 = vb[i0 * 3 + 2];
    float x1 = vb[i1 * 3 + 0], y1 = vb[i1 * 3 + 1], z1 = vb[i1 * 3 + 2];
    float x2 = vb[i2 * 3 + 0], y2 = vb[i2 * 3 + 1], z2 = vb[i2 * 3 + 2];

    // area with reference rounding (no FMA contraction)
    float area = __fsub_rn(__fmul_rn(__fsub_rn(x1, x0), __fsub_rn(y2, y0)),
                           __fmul_rn(__fsub_rn(y1, y0), __fsub_rn(x2, x0)));
    float s = (area > 0.0f) ? 1.0f : -1.0f;
    bool valid = fabsf(area) > 1e-12f;

    float4 bb, e0, e1, e2, wv;
    if (valid) {
        float inv = 1.0f / fabsf(area);
        // store (s*dx, -(s*dy), refx, -refy): negations are exact
        e0 = make_float4(s * __fsub_rn(x2, x1), -(s * __fsub_rn(y2, y1)), x1, -y1);
        e1 = make_float4(s * __fsub_rn(x0, x2), -(s * __fsub_rn(y0, y2)), x2, -y2);
        e2 = make_float4(s * __fsub_rn(x1, x0), -(s * __fsub_rn(y1, y0)), x0, -y0);
        wv = make_float4(z0 * inv, z1 * inv, z2 * inv, 0.0f);
        bb = make_float4(fminf(x0, fminf(x1, x2)), fmaxf(x0, fmaxf(x1, x2)),
                         fminf(y0, fminf(y1, y2)), fmaxf(y0, fmaxf(y1, y2)));
    } else {
        // empty bbox guarantees cull; constants force e' < 0 as backup
        e0 = e1 = e2 = make_float4(0.0f, -1.0f, -4e9f, 0.0f);
        wv = make_float4(0.0f, 0.0f, 0.0f, 0.0f);
        bb = make_float4(3e38f, -3e38f, 3e38f, -3e38f);
    }
    g_bb[idx] = bb;
    g_ed[idx * 4 + 0] = e0;
    g_ed[idx * 4 + 1] = e1;
    g_ed[idx * 4 + 2] = e2;
    g_ed[idx * 4 + 3] = wv;
}

// Raster: one coalesced LDG round into smem, then ballot-compacted raster.
// Warp tile = 16 cols x 16 rows; thread owns an 8-pixel column half.
// Edge functions 2 px/instr via f32x2; sign-bit inside test; atomicMin merge.
__global__ void __launch_bounds__(256) raster_kernel(
    float* __restrict__ out)
{
    __shared__ float4 sbb[CHUNK];          // (xmin, xmax, ymin, ymax)
    __shared__ float4 sed[CHUNK * 4];      // e0,e1,e2,wv per face

    int bz = blockIdx.z;
    int b = bz / NSLICE;
    int slice = bz - b * NSLICE;
    int f0 = slice * CHUNK;
    int nf = min(NF - f0, CHUNK);          // 13 (last slice: 4)

    // ---- Phase 1: single parallel load round (no dependent gather) ----
    int t = threadIdx.x;
    {
        const float4* src = g_ed + (size_t)(b * NF + f0) * 4;
        if (t < nf * 4) sed[t] = src[t];
        else if (t >= 64 && t < 64 + nf) sbb[t - 64] = g_bb[b * NF + f0 + (t - 64)];
    }
    __syncthreads();

    // ---- Phase 2: rasterize. Warp tile = 16 cols x 16 rows. Lane layout:
    //      col = (w&1)*16 + (lane&15), rows = (w>>1)*16 + (lane>>4)*8 .. +7.
    //      CTA tile = 32 cols x 64 rows (8 warps in 2x4). Coords exact fp32.
    int lane = threadIdx.x & 31;
    int w = threadIdx.x >> 5;
    int col = blockIdx.x * 32 + (w & 1) * 16 + (lane & 15);
    int rw = blockIdx.y * 64 + (w >> 1) * 16;        // warp row base
    int row0 = rw + (lane >> 4) * 8;                 // thread row base

    float px = 5.0f * (float)col + 2.5f;
    float py0 = 5.0f * (float)row0 + 2.5f;

    // packed row-pair coordinates (py_k, py_{k+1}) for k = 0,2,4,6
    unsigned long long py2[4];
#pragma unroll
    for (int p = 0; p < 4; p++)
        py2[p] = pk2(py0 + 10.0f * (float)p, py0 + 10.0f * (float)p + 5.0f);

    // warp-uniform tile bounds with rounding margin (16 cols/rows -> 75 px)
    float txmin = 5.0f * (float)(blockIdx.x * 32 + (w & 1) * 16) + 2.5f - 1.0f;
    float txmax = txmin + 75.0f + 2.0f;
    float tymin = 5.0f * (float)rw + 2.5f - 1.0f;
    float tymax = tymin + 75.0f + 2.0f;

    // Scan: lane L tests face L (CHUNK=13 <= 32: one ballot round).
    bool pass = false;
    if (lane < nf) {
        float4 bb = sbb[lane];
        pass = !(bb.y < txmin || bb.x > txmax || bb.w < tymin || bb.z > tymax);
    }
    unsigned int m = __ballot_sync(0xFFFFFFFFu, pass);

    float zb[8] = {BGD, BGD, BGD, BGD, BGD, BGD, BGD, BGD};

    while (m) {
        int f = __ffs(m) - 1;
        m &= m - 1;

        float4 e0 = sed[f * 4 + 0];
        float4 e1 = sed[f * 4 + 1];
        float4 e2 = sed[f * 4 + 2];
        float4 wv = sed[f * 4 + 3];

        // hoisted per-column terms, already negated:
        // (-s*dy)*(px - refx) == -(s*dy*(px - refx)) exactly (RN sign-symmetric)
        float n0 = __fmul_rn(e0.y, __fsub_rn(px, e0.z));
        float n1 = __fmul_rn(e1.y, __fsub_rn(px, e1.z));
        float n2 = __fmul_rn(e2.y, __fsub_rn(px, e2.z));

        // packed per-face constants (dup across both halves)
        unsigned long long ax0 = pk2(e0.x, e0.x), nw0 = pk2(e0.w, e0.w), nn0 = pk2(n0, n0);
        unsigned long long ax1 = pk2(e1.x, e1.x), nw1 = pk2(e1.w, e1.w), nn1 = pk2(n1, n1);
        unsigned long long ax2 = pk2(e2.x, e2.x), nw2 = pk2(e2.w, e2.w), nn2 = pk2(n2, n2);

#pragma unroll
        for (int p = 0; p < 4; p++) {
            // e' = ax*(py + (-ry)) + (-m2): each step RN == scalar sequence
            unsigned long long ea2 = add2(mul2(add2(py2[p], nw0), ax0), nn0);
            unsigned long long eb2 = add2(mul2(add2(py2[p], nw1), ax1), nn1);
            unsigned long long ec2 = add2(mul2(add2(py2[p], nw2), ax2), nn2);

            float eaL, eaH, ebL, ebH, ecL, ecH;
            unpk2(ea2, eaL, eaH);
            unpk2(eb2, ebL, ebH);
            unpk2(ec2, ecL, ecH);

            // inside test: all sign bits clear (e' >= 0; exact -0.0 needs a
            // vertex exactly on the pixel grid in x AND y -- absent here).
            unsigned int sL = __float_as_uint(eaL) | __float_as_uint(ebL) | __float_as_uint(ecL);
            unsigned int sH = __float_as_uint(eaH) | __float_as_uint(ebH) | __float_as_uint(ecH);
            if ((int)sL >= 0) {
                float z = fmaf(eaL, wv.x, fmaf(ebL, wv.y, __fmul_rn(ecL, wv.z)));
                zb[2 * p] = fminf(zb[2 * p], z);
            }
            if ((int)sH >= 0) {
                float z = fmaf(eaH, wv.x, fmaf(ebH, wv.y, __fmul_rn(ecH, wv.z)));
                zb[2 * p + 1] = fminf(zb[2 * p + 1], z);
            }
        }
    }

    // ---- Phase 3: clamp + atomicMin straight into the output.
    //      min(z,100) commutes with the global min; empty stays 100.
    unsigned int* ob = reinterpret_cast<unsigned int*>(out) + ((size_t)b * OH) * OW;
#pragma unroll
    for (int k = 0; k < 8; k++) {
        if (zb[k] < BGD) {
            float cand = fminf(zb[k], 100.0f);
            atomicMin(&ob[(size_t)(row0 + k) * OW + col], __float_as_uint(cand));
        }
    }
}

extern "C" void kernel_launch(void* const* d_in, const int* in_sizes, int n_in,
                              void* d_out, int out_size)
{
    const float* verts = (const float*)d_in[0];
    const int* faces = (const int*)d_in[1];
    float* out = (float*)d_out;

    setup_kernel<<<64, 256>>>(verts, faces, out);   // out-fill + 6152 records

    dim3 grid(OW / 32, OH / 64, NB * NSLICE);       // (4, 2, 476) = 3808 CTAs
    raster_kernel<<<grid, 256>>>(out);
}

// round 16
// speedup vs baseline: 1.0200x; 1.0200x over previous
#include <cuda_runtime.h>
#include <cstdint>

#define NV 778
#define NF 1538
#define NB 4
#define OW 128
#define OH 128
#define BGD 1e10f
#define CHUNK 26
#define NSLICE ((NF + CHUNK - 1) / CHUNK)         // 60 (last slice: 4 faces)
#define NPIX (NB * OH * OW)                       // 65536

// Precomputed face records (SoA): bbox + 4 float4 (e0,e1,e2,wv) per (b,f).
//   e: (s*dx, -(s*dy), refx, -refy)
//      e' = (s*dx)*(py + (-refy)) + [(-s*dy)*(px - refx)]
//   wv: (z0/|area|, z1/|area|, z2/|area|, 0)
__device__ float4 g_bb[NB * NF];
__device__ float4 g_ed[NB * NF * 4];

// Packed f32x2 helpers: component-wise IEEE-RN, bit-identical to scalar RN ops.
__device__ __forceinline__ unsigned long long pk2(float lo, float hi) {
    unsigned long long r;
    asm("mov.b64 %0, {%1, %2};" : "=l"(r) : "r"(__float_as_uint(lo)), "r"(__float_as_uint(hi)));
    return r;
}
__device__ __forceinline__ unsigned long long mul2(unsigned long long a, unsigned long long b) {
    unsigned long long r;
    asm("mul.rn.f32x2 %0, %1, %2;" : "=l"(r) : "l"(a), "l"(b));
    return r;
}
__device__ __forceinline__ unsigned long long add2(unsigned long long a, unsigned long long b) {
    unsigned long long r;
    asm("add.rn.f32x2 %0, %1, %2;" : "=l"(r) : "l"(a), "l"(b));
    return r;
}
__device__ __forceinline__ void unpk2(unsigned long long v, float& lo, float& hi) {
    unsigned int a, b;
    asm("mov.b64 {%0, %1}, %2;" : "=r"(a), "=r"(b) : "l"(v));
    lo = __uint_as_float(a); hi = __uint_as_float(b);
}

// Fused precompute: fill out with 100.0f AND build all face records.
__global__ void __launch_bounds__(256) setup_kernel(
    const float* __restrict__ verts, const int* __restrict__ faces,
    float* __restrict__ out)
{
    int idx = blockIdx.x * blockDim.x + threadIdx.x;

    if (idx < NPIX / 4) {
        float4 v = make_float4(100.0f, 100.0f, 100.0f, 100.0f);
        reinterpret_cast<float4*>(out)[idx] = v;
    }

    if (idx >= NB * NF) return;
    int b = idx / NF;
    int f = idx - b * NF;

    // faces land on device as int32 (JAX x64 disabled). Clamp defensively.
    int i0 = min(max(faces[f * 3 + 0], 0), NV - 1);
    int i1 = min(max(faces[f * 3 + 1], 0), NV - 1);
    int i2 = min(max(faces[f * 3 + 2], 0), NV - 1);
    const float* vb = verts + (size_t)b * NV * 3;
    float x0 = vb[i0 * 3 + 0], y0 = vb[i0 * 3 + 1], z0 = vb[i0 * 3 + 2];
    float x1 = vb[i1 * 3 + 0], y1 = vb[i1 * 3 + 1], z1 = vb[i1 * 3 + 2];
    float x2 = vb[i2 * 3 + 0], y2 = vb[i2 * 3 + 1], z2 = vb[i2 * 3 + 2];

    // area with reference rounding (no FMA contraction)
    float area = __fsub_rn(__fmul_rn(__fsub_rn(x1, x0), __fsub_rn(y2, y0)),
                           __fmul_rn(__fsub_rn(y1, y0), __fsub_rn(x2, x0)));
    float s = (area > 0.0f) ? 1.0f : -1.0f;
    bool valid = fabsf(area) > 1e-12f;

    float4 bb, e0, e1, e2, wv;
    if (valid) {
        float inv = 1.0f / fabsf(area);
        // store (s*dx, -(s*dy), refx, -refy): negations are exact
        e0 = make_float4(s * __fsub_rn(x2, x1), -(s * __fsub_rn(y2, y1)), x1, -y1);
        e1 = make_float4(s * __fsub_rn(x0, x2), -(s * __fsub_rn(y0, y2)), x2, -y2);
        e2 = make_float4(s * __fsub_rn(x1, x0), -(s * __fsub_rn(y1, y0)), x0, -y0);
        wv = make_float4(z0 * inv, z1 * inv, z2 * inv, 0.0f);
        bb = make_float4(fminf(x0, fminf(x1, x2)), fmaxf(x0, fmaxf(x1, x2)),
                         fminf(y0, fminf(y1, y2)), fmaxf(y0, fmaxf(y1, y2)));
    } else {
        // empty bbox guarantees cull; constants force e' < 0 as backup
        e0 = e1 = e2 = make_float4(0.0f, -1.0f, -4e9f, 0.0f);
        wv = make_float4(0.0f, 0.0f, 0.0f, 0.0f);
        bb = make_float4(3e38f, -3e38f, 3e38f, -3e38f);
    }
    g_bb[idx] = bb;
    g_ed[idx * 4 + 0] = e0;
    g_ed[idx * 4 + 1] = e1;
    g_ed[idx * 4 + 2] = e2;
    g_ed[idx * 4 + 3] = wv;
}

// Raster: one coalesced LDG round into smem, then ballot-compacted raster.
// Warp tile = 16 cols x 16 rows; thread owns an 8-pixel column half.
// Edge functions 2 px/instr via f32x2; sign-bit inside test; atomicMin merge.
__global__ void __launch_bounds__(256) raster_kernel(
    float* __restrict__ out)
{
    __shared__ float4 sbb[CHUNK];          // (xmin, xmax, ymin, ymax)
    __shared__ float4 sed[CHUNK * 4];      // e0,e1,e2,wv per face

    int bz = blockIdx.z;
    int b = bz / NSLICE;
    int slice = bz - b * NSLICE;
    int f0 = slice * CHUNK;
    int nf = min(NF - f0, CHUNK);          // 26 (last slice: 4)

    // ---- Phase 1: single parallel load round (no dependent gather) ----
    int t = threadIdx.x;
    {
        const float4* src = g_ed + (size_t)(b * NF + f0) * 4;
        if (t < nf * 4) sed[t] = src[t];
        else if (t >= 128 && t < 128 + nf) sbb[t - 128] = g_bb[b * NF + f0 + (t - 128)];
    }
    __syncthreads();

    // ---- Phase 2: rasterize. Warp tile = 16 cols x 16 rows. Lane layout:
    //      col = (w&1)*16 + (lane&15), rows = (w>>1)*16 + (lane>>4)*8 .. +7.
    //      CTA tile = 32 cols x 64 rows (8 warps in 2x4). Coords exact fp32.
    int lane = threadIdx.x & 31;
    int w = threadIdx.x >> 5;
    int col = blockIdx.x * 32 + (w & 1) * 16 + (lane & 15);
    int rw = blockIdx.y * 64 + (w >> 1) * 16;        // warp row base
    int row0 = rw + (lane >> 4) * 8;                 // thread row base

    float px = 5.0f * (float)col + 2.5f;
    float py0 = 5.0f * (float)row0 + 2.5f;

    // packed row-pair coordinates (py_k, py_{k+1}) for k = 0,2,4,6
    unsigned long long py2[4];
#pragma unroll
    for (int p = 0; p < 4; p++)
        py2[p] = pk2(py0 + 10.0f * (float)p, py0 + 10.0f * (float)p + 5.0f);

    // warp-uniform tile bounds with rounding margin (16 cols/rows -> 75 px)
    float txmin = 5.0f * (float)(blockIdx.x * 32 + (w & 1) * 16) + 2.5f - 1.0f;
    float txmax = txmin + 75.0f + 2.0f;
    float tymin = 5.0f * (float)rw + 2.5f - 1.0f;
    float tymax = tymin + 75.0f + 2.0f;

    // Scan: lane L tests face L (CHUNK=26 <= 32: single ballot round).
    bool pass = false;
    if (lane < nf) {
        float4 bb = sbb[lane];
        pass = !(bb.y < txmin || bb.x > txmax || bb.w < tymin || bb.z > tymax);
    }
    unsigned int m = __ballot_sync(0xFFFFFFFFu, pass);

    float zb[8] = {BGD, BGD, BGD, BGD, BGD, BGD, BGD, BGD};

    while (m) {
        int f = __ffs(m) - 1;
        m &= m - 1;

        float4 e0 = sed[f * 4 + 0];
        float4 e1 = sed[f * 4 + 1];
        float4 e2 = sed[f * 4 + 2];
        float4 wv = sed[f * 4 + 3];

        // hoisted per-column terms, already negated:
        // (-s*dy)*(px - refx) == -(s*dy*(px - refx)) exactly (RN sign-symmetric)
        float n0 = __fmul_rn(e0.y, __fsub_rn(px, e0.z));
        float n1 = __fmul_rn(e1.y, __fsub_rn(px, e1.z));
        float n2 = __fmul_rn(e2.y, __fsub_rn(px, e2.z));

        // packed per-face constants (dup across both halves)
        unsigned long long ax0 = pk2(e0.x, e0.x), nw0 = pk2(e0.w, e0.w), nn0 = pk2(n0, n0);
        unsigned long long ax1 = pk2(e1.x, e1.x), nw1 = pk2(e1.w, e1.w), nn1 = pk2(n1, n1);
        unsigned long long ax2 = pk2(e2.x, e2.x), nw2 = pk2(e2.w, e2.w), nn2 = pk2(n2, n2);

#pragma unroll
        for (int p = 0; p < 4; p++) {
            // e' = ax*(py + (-ry)) + (-m2): each step RN == scalar sequence
            unsigned long long ea2 = add2(mul2(add2(py2[p], nw0), ax0), nn0);
            unsigned long long eb2 = add2(mul2(add2(py2[p], nw1), ax1), nn1);
            unsigned long long ec2 = add2(mul2(add2(py2[p], nw2), ax2), nn2);

            float eaL, eaH, ebL, ebH, ecL, ecH;
            unpk2(ea2, eaL, eaH);
            unpk2(eb2, ebL, ebH);
            unpk2(ec2, ecL, ecH);

            // inside test: all sign bits clear (e' >= 0; exact -0.0 needs a
            // vertex exactly on the pixel grid in x AND y -- absent here).
            unsigned int sL = __float_as_uint(eaL) | __float_as_uint(ebL) | __float_as_uint(ecL);
            unsigned int sH = __float_as_uint(eaH) | __float_as_uint(ebH) | __float_as_uint(ecH);
            if ((int)sL >= 0) {
                float z = fmaf(eaL, wv.x, fmaf(ebL, wv.y, __fmul_rn(ecL, wv.z)));
                zb[2 * p] = fminf(zb[2 * p], z);
            }
            if ((int)sH >= 0) {
                float z = fmaf(eaH, wv.x, fmaf(ebH, wv.y, __fmul_rn(ecH, wv.z)));
                zb[2 * p + 1] = fminf(zb[2 * p + 1], z);
            }
        }
    }

    // ---- Phase 3: clamp + atomicMin straight into the output.
    //      min(z,100) commutes with the global min; empty stays 100.
    unsigned int* ob = reinterpret_cast<unsigned int*>(out) + ((size_t)b * OH) * OW;
#pragma unroll
    for (int k = 0; k < 8; k++) {
        if (zb[k] < BGD) {
            float cand = fminf(zb[k], 100.0f);
            atomicMin(&ob[(size_t)(row0 + k) * OW + col], __float_as_uint(cand));
        }
    }
}

extern "C" void kernel_launch(void* const* d_in, const int* in_sizes, int n_in,
                              void* d_out, int out_size)
{
    const float* verts = (const float*)d_in[0];
    const int* faces = (const int*)d_in[1];
    float* out = (float*)d_out;

    setup_kernel<<<64, 256>>>(verts, faces, out);   // out-fill + 6152 records

    dim3 grid(OW / 32, OH / 64, NB * NSLICE);       // (4, 2, 240) = 1920 CTAs
    raster_kernel<<<grid, 256>>>(out);
}